// round 1
// baseline (speedup 1.0000x reference)
#include <cuda_runtime.h>
#include <math.h>
#include <float.h>

#define N_NODES 100000
#define IN_DIM  256
#define HID     128
#define OUT_DIM 40

// Scratch (allocation-free: device globals)
__device__ float g_deg_out[N_NODES];
__device__ float g_deg_in[N_NODES];
__device__ float g_buf1[(size_t)N_NODES * HID];  // h1 (layer1 pre-agg), later x2 (layer2 pre-agg)
__device__ float g_buf2[(size_t)N_NODES * HID];  // agg1 -> x1 (in place)

__device__ __forceinline__ void red_add_v4(float* p, float4 v) {
    asm volatile("red.global.add.v4.f32 [%0], {%1,%2,%3,%4};"
                 :: "l"(p), "f"(v.x), "f"(v.y), "f"(v.z), "f"(v.w) : "memory");
}

// ---------------------------------------------------------------------------
// Zero all accumulators (deg, agg1, out-as-agg2)
// ---------------------------------------------------------------------------
__global__ void zero_kernel(float4* __restrict__ out4) {
    size_t tid = (size_t)blockIdx.x * blockDim.x + threadIdx.x;
    size_t stride = (size_t)gridDim.x * blockDim.x;
    float4 z = make_float4(0.f, 0.f, 0.f, 0.f);
    float4* b2 = reinterpret_cast<float4*>(g_buf2);
    for (size_t i = tid; i < (size_t)N_NODES * HID / 4; i += stride) b2[i] = z;
    for (size_t i = tid; i < (size_t)N_NODES * OUT_DIM / 4; i += stride) out4[i] = z;
    float4* dout = reinterpret_cast<float4*>(g_deg_out);
    float4* din  = reinterpret_cast<float4*>(g_deg_in);
    for (size_t i = tid; i < N_NODES / 4; i += stride) { dout[i] = z; din[i] = z; }
}

// ---------------------------------------------------------------------------
// Degrees
// ---------------------------------------------------------------------------
__global__ void degree_kernel(const int* __restrict__ src, const int* __restrict__ dst, int E) {
    int i = blockIdx.x * blockDim.x + threadIdx.x;
    if (i >= E) return;
    atomicAdd(&g_deg_out[src[i]], 1.0f);
    atomicAdd(&g_deg_in[dst[i]], 1.0f);
}

// ---------------------------------------------------------------------------
// GEMM1: g_buf1 = (h @ W1) * rsqrt(max(deg_out,1))   [100000 x 256] x [256 x 128]
// BM=64 BN=128 BK=16, 128 threads, 8x8 register tiles
// ---------------------------------------------------------------------------
#define G1_BM 64
#define G1_BK 16
__global__ __launch_bounds__(128) void gemm1_kernel(const float* __restrict__ A,
                                                    const float* __restrict__ B) {
    __shared__ float As[G1_BK][G1_BM];
    __shared__ float Bs[G1_BK][HID];
    const int tid = threadIdx.x;
    const int row0 = blockIdx.x * G1_BM;
    const int tm0 = (tid >> 4) * 8;      // 0..56
    const int tn0 = (tid & 15) * 8;      // 0..120
    const int ar = tid >> 2, ac = tid & 3;   // A load: 32 rows x 4 float4-chunks
    const int bk = tid >> 5, bc = tid & 31;  // B load: 4 k-rows x 32 float4-chunks

    float acc[8][8];
#pragma unroll
    for (int i = 0; i < 8; i++)
#pragma unroll
        for (int j = 0; j < 8; j++) acc[i][j] = 0.f;

    for (int k0 = 0; k0 < IN_DIM; k0 += G1_BK) {
#pragma unroll
        for (int rr = 0; rr < 2; rr++) {
            int row = row0 + ar + rr * 32;
            float4 v = make_float4(0.f, 0.f, 0.f, 0.f);
            if (row < N_NODES)
                v = *reinterpret_cast<const float4*>(A + (size_t)row * IN_DIM + k0 + ac * 4);
            As[ac * 4 + 0][ar + rr * 32] = v.x;
            As[ac * 4 + 1][ar + rr * 32] = v.y;
            As[ac * 4 + 2][ar + rr * 32] = v.z;
            As[ac * 4 + 3][ar + rr * 32] = v.w;
        }
#pragma unroll
        for (int i = 0; i < 4; i++) {
            float4 v = *reinterpret_cast<const float4*>(B + (size_t)(k0 + bk + 4 * i) * HID + bc * 4);
            *reinterpret_cast<float4*>(&Bs[bk + 4 * i][bc * 4]) = v;
        }
        __syncthreads();
#pragma unroll
        for (int k = 0; k < G1_BK; k++) {
            float ra[8], rb[8];
#pragma unroll
            for (int i = 0; i < 8; i++) ra[i] = As[k][tm0 + i];
#pragma unroll
            for (int j = 0; j < 8; j++) rb[j] = Bs[k][tn0 + j];
#pragma unroll
            for (int i = 0; i < 8; i++)
#pragma unroll
                for (int j = 0; j < 8; j++) acc[i][j] += ra[i] * rb[j];
        }
        __syncthreads();
    }

#pragma unroll
    for (int i = 0; i < 8; i++) {
        int row = row0 + tm0 + i;
        if (row >= N_NODES) break;
        float s = rsqrtf(fmaxf(g_deg_out[row], 1.0f));
#pragma unroll
        for (int j = 0; j < 8; j += 4) {
            float4 v = make_float4(acc[i][j] * s, acc[i][j + 1] * s,
                                   acc[i][j + 2] * s, acc[i][j + 3] * s);
            *reinterpret_cast<float4*>(g_buf1 + (size_t)row * HID + tn0 + j) = v;
        }
    }
}

// ---------------------------------------------------------------------------
// SpMM1: g_buf2[dst] += g_buf1[src], warp per edge, 128 floats = 32 lanes x float4
// ---------------------------------------------------------------------------
__global__ void spmm1_kernel(const int* __restrict__ src, const int* __restrict__ dst, int E) {
    int w = (blockIdx.x * blockDim.x + threadIdx.x) >> 5;
    if (w >= E) return;
    int lane = threadIdx.x & 31;
    int s = __ldg(&src[w]);
    int d = __ldg(&dst[w]);
    float4 v = *reinterpret_cast<const float4*>(g_buf1 + (size_t)s * HID + lane * 4);
    red_add_v4(g_buf2 + (size_t)d * HID + lane * 4, v);
}

// ---------------------------------------------------------------------------
// x1 = relu(agg1 * rsqrt(max(deg_in,1)) + b1)   (in place on g_buf2)
// ---------------------------------------------------------------------------
__global__ void relu_bias_kernel(const float* __restrict__ b1) {
    int idx = blockIdx.x * blockDim.x + threadIdx.x;  // float4 index
    if (idx >= N_NODES * (HID / 4)) return;
    int row = idx >> 5;            // 32 float4 per row
    int colq = idx & 31;
    float s = rsqrtf(fmaxf(g_deg_in[row], 1.0f));
    float4 v = reinterpret_cast<float4*>(g_buf2)[idx];
    float4 bb = *reinterpret_cast<const float4*>(b1 + colq * 4);
    v.x = fmaxf(v.x * s + bb.x, 0.f);
    v.y = fmaxf(v.y * s + bb.y, 0.f);
    v.z = fmaxf(v.z * s + bb.z, 0.f);
    v.w = fmaxf(v.w * s + bb.w, 0.f);
    reinterpret_cast<float4*>(g_buf2)[idx] = v;
}

// ---------------------------------------------------------------------------
// GEMM2: g_buf1[:, :40] = (x1 @ W2) * rsqrt(max(deg_out,1))
// W2 (128x40 = 20KB) in smem, thread-per-row, acc[40] in registers.
// ---------------------------------------------------------------------------
__global__ __launch_bounds__(128) void gemm2_kernel(const float* __restrict__ W2) {
    __shared__ float Ws[HID * OUT_DIM];  // 5120 floats
    const int tid = threadIdx.x;
    for (int i = tid; i < HID * OUT_DIM; i += 128) Ws[i] = W2[i];
    __syncthreads();

    int row = blockIdx.x * 128 + tid;
    if (row >= N_NODES) return;

    float acc[OUT_DIM];
#pragma unroll
    for (int c = 0; c < OUT_DIM; c++) acc[c] = 0.f;

    const float* xr = g_buf2 + (size_t)row * HID;
#pragma unroll 4
    for (int k = 0; k < HID; k += 4) {
        float4 xv = *reinterpret_cast<const float4*>(xr + k);
        const float* w0 = &Ws[(k + 0) * OUT_DIM];
        const float* w1 = &Ws[(k + 1) * OUT_DIM];
        const float* w2 = &Ws[(k + 2) * OUT_DIM];
        const float* w3 = &Ws[(k + 3) * OUT_DIM];
#pragma unroll
        for (int c = 0; c < OUT_DIM; c++)
            acc[c] += xv.x * w0[c] + xv.y * w1[c] + xv.z * w2[c] + xv.w * w3[c];
    }

    float s = rsqrtf(fmaxf(g_deg_out[row], 1.0f));
    float* o = g_buf1 + (size_t)row * OUT_DIM;
#pragma unroll
    for (int c = 0; c < OUT_DIM; c++) o[c] = acc[c] * s;
}

// ---------------------------------------------------------------------------
// SpMM2: out[dst] += x2[src]; 40 floats = 10 float4 chunks; thread per (edge,chunk)
// ---------------------------------------------------------------------------
__global__ void spmm2_kernel(const int* __restrict__ src, const int* __restrict__ dst,
                             float* __restrict__ out, int E) {
    int i = blockIdx.x * blockDim.x + threadIdx.x;
    if (i >= E * 10) return;
    int e = i / 10, c = i % 10;
    int s = __ldg(&src[e]);
    int d = __ldg(&dst[e]);
    float4 v = *reinterpret_cast<const float4*>(g_buf1 + (size_t)s * OUT_DIM + c * 4);
    red_add_v4(out + (size_t)d * OUT_DIM + c * 4, v);
}

// ---------------------------------------------------------------------------
// finalize: out = log_softmax(agg2 * rsqrt(max(deg_in,1)) + b2), warp per row
// ---------------------------------------------------------------------------
__global__ void finalize_kernel(float* __restrict__ out, const float* __restrict__ b2) {
    int row = (blockIdx.x * blockDim.x + threadIdx.x) >> 5;
    if (row >= N_NODES) return;
    int lane = threadIdx.x & 31;
    float s = rsqrtf(fmaxf(g_deg_in[row], 1.0f));
    float* r = out + (size_t)row * OUT_DIM;

    float x0 = r[lane] * s + b2[lane];
    bool has2 = lane < (OUT_DIM - 32);
    float x1 = has2 ? (r[32 + lane] * s + b2[32 + lane]) : -FLT_MAX;

    float m = fmaxf(x0, x1);
#pragma unroll
    for (int o = 16; o > 0; o >>= 1) m = fmaxf(m, __shfl_xor_sync(0xffffffff, m, o));

    float se = expf(x0 - m) + (has2 ? expf(x1 - m) : 0.f);
#pragma unroll
    for (int o = 16; o > 0; o >>= 1) se += __shfl_xor_sync(0xffffffff, se, o);

    float lse = m + logf(se);
    r[lane] = x0 - lse;
    if (has2) r[32 + lane] = x1 - lse;
}

// ---------------------------------------------------------------------------
extern "C" void kernel_launch(void* const* d_in, const int* in_sizes, int n_in,
                              void* d_out, int out_size) {
    const float* h  = (const float*)d_in[0];
    const float* W1 = (const float*)d_in[1];
    const float* b1 = (const float*)d_in[2];
    const float* W2 = (const float*)d_in[3];
    const float* b2 = (const float*)d_in[4];
    const int* src  = (const int*)d_in[5];
    const int* dst  = (const int*)d_in[6];
    float* out      = (float*)d_out;
    const int E     = in_sizes[5];

    zero_kernel<<<4096, 256>>>(reinterpret_cast<float4*>(out));
    degree_kernel<<<(E + 255) / 256, 256>>>(src, dst, E);
    gemm1_kernel<<<(N_NODES + G1_BM - 1) / G1_BM, 128>>>(h, W1);
    {
        long long threads = (long long)E * 32;
        int blocks = (int)((threads + 255) / 256);
        spmm1_kernel<<<blocks, 256>>>(src, dst, E);
    }
    relu_bias_kernel<<<(N_NODES * (HID / 4) + 255) / 256, 256>>>(b1);
    gemm2_kernel<<<(N_NODES + 127) / 128, 128>>>(W2);
    {
        long long threads = (long long)E * 10;
        int blocks = (int)((threads + 255) / 256);
        spmm2_kernel<<<blocks, 256>>>(src, dst, out, E);
    }
    finalize_kernel<<<(N_NODES * 32 + 255) / 256, 256>>>(out, b2);
}

// round 2
// speedup vs baseline: 1.6189x; 1.6189x over previous
#include <cuda_runtime.h>
#include <math.h>
#include <float.h>

#define N_NODES 100000
#define IN_DIM  256
#define HID     128
#define OUT_DIM 40
#define E_MAX   3200000
#define NB_SCAN ((N_NODES + 1023) / 1024)   // 98

// ---------------- scratch (device globals, allocation-free) ----------------
__device__ int   g_cnt_in[N_NODES];
__device__ int   g_cnt_out[N_NODES];
__device__ int   g_incl[N_NODES];          // inclusive scan of cnt_in within block
__device__ int   g_bsum[NB_SCAN];
__device__ int   g_boff[NB_SCAN];
__device__ int   g_row_off[N_NODES + 1];   // CSR offsets (dst-grouped)
__device__ int   g_cursor[N_NODES];
__device__ int   g_csr_src[E_MAX];         // src node per CSR slot
__device__ float g_buf1[(size_t)N_NODES * HID];  // h1 = (h@W1)*dout^-1/2 ; later x2 (stride 40)
__device__ float g_buf2[(size_t)N_NODES * HID];  // x1 = relu(norm(agg1)+b1)

// ---------------------------------------------------------------------------
__global__ void zero_counts_kernel() {
    int i = blockIdx.x * blockDim.x + threadIdx.x;
    if (i < N_NODES) { g_cnt_in[i] = 0; g_cnt_out[i] = 0; }
}

__global__ void degree_kernel(const int* __restrict__ src, const int* __restrict__ dst, int E) {
    int i = blockIdx.x * blockDim.x + threadIdx.x;
    if (i >= E) return;
    atomicAdd(&g_cnt_out[src[i]], 1);
    atomicAdd(&g_cnt_in[dst[i]], 1);
}

// ---------------- CSR build: scan of cnt_in, then scatter ----------------
__global__ __launch_bounds__(1024) void scan1_kernel() {
    __shared__ int sh[1024];
    int i = blockIdx.x * 1024 + threadIdx.x;
    int v = (i < N_NODES) ? g_cnt_in[i] : 0;
    sh[threadIdx.x] = v;
    __syncthreads();
#pragma unroll
    for (int o = 1; o < 1024; o <<= 1) {
        int t = (threadIdx.x >= o) ? sh[threadIdx.x - o] : 0;
        __syncthreads();
        sh[threadIdx.x] += t;
        __syncthreads();
    }
    if (i < N_NODES) g_incl[i] = sh[threadIdx.x];
    if (threadIdx.x == 1023) g_bsum[blockIdx.x] = sh[1023];
}

__global__ void scan2_kernel() {
    if (threadIdx.x == 0 && blockIdx.x == 0) {
        int acc = 0;
        for (int b = 0; b < NB_SCAN; b++) { g_boff[b] = acc; acc += g_bsum[b]; }
    }
}

__global__ void scan3_kernel() {
    int i = blockIdx.x * blockDim.x + threadIdx.x;
    if (i >= N_NODES) return;
    int boff = g_boff[i >> 10];
    int excl = g_incl[i] - g_cnt_in[i] + boff;
    g_row_off[i] = excl;
    g_cursor[i]  = excl;
    if (i == N_NODES - 1) g_row_off[N_NODES] = g_incl[i] + boff;
}

__global__ void scatter_kernel(const int* __restrict__ src, const int* __restrict__ dst, int E) {
    int e = blockIdx.x * blockDim.x + threadIdx.x;
    if (e >= E) return;
    int d = dst[e];
    int pos = atomicAdd(&g_cursor[d], 1);
    g_csr_src[pos] = src[e];
}

// ---------------------------------------------------------------------------
// GEMM1: g_buf1 = (h @ W1) * rsqrt(max(deg_out,1))
// ---------------------------------------------------------------------------
#define G1_BM 64
#define G1_BK 16
__global__ __launch_bounds__(128) void gemm1_kernel(const float* __restrict__ A,
                                                    const float* __restrict__ B) {
    __shared__ float As[G1_BK][G1_BM];
    __shared__ float Bs[G1_BK][HID];
    const int tid = threadIdx.x;
    const int row0 = blockIdx.x * G1_BM;
    const int tm0 = (tid >> 4) * 8;
    const int tn0 = (tid & 15) * 8;
    const int ar = tid >> 2, ac = tid & 3;
    const int bk = tid >> 5, bc = tid & 31;

    float acc[8][8];
#pragma unroll
    for (int i = 0; i < 8; i++)
#pragma unroll
        for (int j = 0; j < 8; j++) acc[i][j] = 0.f;

    for (int k0 = 0; k0 < IN_DIM; k0 += G1_BK) {
#pragma unroll
        for (int rr = 0; rr < 2; rr++) {
            int row = row0 + ar + rr * 32;
            float4 v = make_float4(0.f, 0.f, 0.f, 0.f);
            if (row < N_NODES)
                v = *reinterpret_cast<const float4*>(A + (size_t)row * IN_DIM + k0 + ac * 4);
            As[ac * 4 + 0][ar + rr * 32] = v.x;
            As[ac * 4 + 1][ar + rr * 32] = v.y;
            As[ac * 4 + 2][ar + rr * 32] = v.z;
            As[ac * 4 + 3][ar + rr * 32] = v.w;
        }
#pragma unroll
        for (int i = 0; i < 4; i++) {
            float4 v = *reinterpret_cast<const float4*>(B + (size_t)(k0 + bk + 4 * i) * HID + bc * 4);
            *reinterpret_cast<float4*>(&Bs[bk + 4 * i][bc * 4]) = v;
        }
        __syncthreads();
#pragma unroll
        for (int k = 0; k < G1_BK; k++) {
            float ra[8], rb[8];
#pragma unroll
            for (int i = 0; i < 8; i++) ra[i] = As[k][tm0 + i];
#pragma unroll
            for (int j = 0; j < 8; j++) rb[j] = Bs[k][tn0 + j];
#pragma unroll
            for (int i = 0; i < 8; i++)
#pragma unroll
                for (int j = 0; j < 8; j++) acc[i][j] += ra[i] * rb[j];
        }
        __syncthreads();
    }

#pragma unroll
    for (int i = 0; i < 8; i++) {
        int row = row0 + tm0 + i;
        if (row >= N_NODES) break;
        float s = rsqrtf(fmaxf((float)g_cnt_out[row], 1.0f));
#pragma unroll
        for (int j = 0; j < 8; j += 4) {
            float4 v = make_float4(acc[i][j] * s, acc[i][j + 1] * s,
                                   acc[i][j + 2] * s, acc[i][j + 3] * s);
            *reinterpret_cast<float4*>(g_buf1 + (size_t)row * HID + tn0 + j) = v;
        }
    }
}

// ---------------------------------------------------------------------------
// SpMM1 (pull, CSR): warp per dst node. acc in registers, fused norm+bias+relu.
// ---------------------------------------------------------------------------
__global__ __launch_bounds__(256) void spmm1_csr_kernel(const float* __restrict__ b1) {
    int n = (blockIdx.x * blockDim.x + threadIdx.x) >> 5;
    if (n >= N_NODES) return;
    int lane = threadIdx.x & 31;
    int start = g_row_off[n];
    int end   = g_row_off[n + 1];

    float ax = 0.f, ay = 0.f, az = 0.f, aw = 0.f;
    for (int j = start; j < end; j += 32) {
        int s = 0;
        if (j + lane < end) s = __ldg(&g_csr_src[j + lane]);
        int cnt = min(32, end - j);
        for (int k = 0; k < cnt; k++) {
            int sv = __shfl_sync(0xffffffff, s, k);
            float4 v = *reinterpret_cast<const float4*>(g_buf1 + (size_t)sv * HID + lane * 4);
            ax += v.x; ay += v.y; az += v.z; aw += v.w;
        }
    }

    float sc = rsqrtf(fmaxf((float)(end - start), 1.0f));  // deg_in norm
    float4 bb = *reinterpret_cast<const float4*>(b1 + lane * 4);
    float4 o;
    o.x = fmaxf(ax * sc + bb.x, 0.f);
    o.y = fmaxf(ay * sc + bb.y, 0.f);
    o.z = fmaxf(az * sc + bb.z, 0.f);
    o.w = fmaxf(aw * sc + bb.w, 0.f);
    *reinterpret_cast<float4*>(g_buf2 + (size_t)n * HID + lane * 4) = o;
}

// ---------------------------------------------------------------------------
// GEMM2: g_buf1[:, :40] = (x1 @ W2) * rsqrt(max(deg_out,1))  (stride OUT_DIM)
// ---------------------------------------------------------------------------
__global__ __launch_bounds__(128) void gemm2_kernel(const float* __restrict__ W2) {
    __shared__ float Ws[HID * OUT_DIM];
    const int tid = threadIdx.x;
    for (int i = tid; i < HID * OUT_DIM; i += 128) Ws[i] = W2[i];
    __syncthreads();

    int row = blockIdx.x * 128 + tid;
    if (row >= N_NODES) return;

    float acc[OUT_DIM];
#pragma unroll
    for (int c = 0; c < OUT_DIM; c++) acc[c] = 0.f;

    const float* xr = g_buf2 + (size_t)row * HID;
#pragma unroll 4
    for (int k = 0; k < HID; k += 4) {
        float4 xv = *reinterpret_cast<const float4*>(xr + k);
        const float* w0 = &Ws[(k + 0) * OUT_DIM];
        const float* w1 = &Ws[(k + 1) * OUT_DIM];
        const float* w2 = &Ws[(k + 2) * OUT_DIM];
        const float* w3 = &Ws[(k + 3) * OUT_DIM];
#pragma unroll
        for (int c = 0; c < OUT_DIM; c++)
            acc[c] += xv.x * w0[c] + xv.y * w1[c] + xv.z * w2[c] + xv.w * w3[c];
    }

    float s = rsqrtf(fmaxf((float)g_cnt_out[row], 1.0f));
    float* o = g_buf1 + (size_t)row * OUT_DIM;
#pragma unroll
    for (int c = 0; c < OUT_DIM; c++) o[c] = acc[c] * s;
}

// ---------------------------------------------------------------------------
// SpMM2 (pull, CSR) + fused norm + bias + log_softmax. Warp per dst node,
// lanes 0..9 each own a float4 chunk of the 40 outputs.
// ---------------------------------------------------------------------------
__global__ __launch_bounds__(256) void spmm2_csr_kernel(float* __restrict__ out,
                                                        const float* __restrict__ b2) {
    int n = (blockIdx.x * blockDim.x + threadIdx.x) >> 5;
    if (n >= N_NODES) return;
    int lane = threadIdx.x & 31;
    bool act = lane < (OUT_DIM / 4);   // lanes 0..9
    int start = g_row_off[n];
    int end   = g_row_off[n + 1];

    float ax = 0.f, ay = 0.f, az = 0.f, aw = 0.f;
    for (int j = start; j < end; j += 32) {
        int s = 0;
        if (j + lane < end) s = __ldg(&g_csr_src[j + lane]);
        int cnt = min(32, end - j);
        for (int k = 0; k < cnt; k++) {
            int sv = __shfl_sync(0xffffffff, s, k);
            if (act) {
                float4 v = *reinterpret_cast<const float4*>(g_buf1 + (size_t)sv * OUT_DIM + lane * 4);
                ax += v.x; ay += v.y; az += v.z; aw += v.w;
            }
        }
    }

    float sc = rsqrtf(fmaxf((float)(end - start), 1.0f));
    float4 x = make_float4(-FLT_MAX, -FLT_MAX, -FLT_MAX, -FLT_MAX);
    if (act) {
        float4 bb = *reinterpret_cast<const float4*>(b2 + lane * 4);
        x.x = ax * sc + bb.x;
        x.y = ay * sc + bb.y;
        x.z = az * sc + bb.z;
        x.w = aw * sc + bb.w;
    }

    // log_softmax across the 40 values spread over lanes 0..9
    float m = fmaxf(fmaxf(x.x, x.y), fmaxf(x.z, x.w));
#pragma unroll
    for (int o = 16; o > 0; o >>= 1) m = fmaxf(m, __shfl_xor_sync(0xffffffff, m, o));

    float se = 0.f;
    if (act) se = expf(x.x - m) + expf(x.y - m) + expf(x.z - m) + expf(x.w - m);
#pragma unroll
    for (int o = 16; o > 0; o >>= 1) se += __shfl_xor_sync(0xffffffff, se, o);

    float lse = m + logf(se);
    if (act) {
        float4 r = make_float4(x.x - lse, x.y - lse, x.z - lse, x.w - lse);
        *reinterpret_cast<float4*>(out + (size_t)n * OUT_DIM + lane * 4) = r;
    }
}

// ---------------------------------------------------------------------------
extern "C" void kernel_launch(void* const* d_in, const int* in_sizes, int n_in,
                              void* d_out, int out_size) {
    const float* h  = (const float*)d_in[0];
    const float* W1 = (const float*)d_in[1];
    const float* b1 = (const float*)d_in[2];
    const float* W2 = (const float*)d_in[3];
    const float* b2 = (const float*)d_in[4];
    const int* src  = (const int*)d_in[5];
    const int* dst  = (const int*)d_in[6];
    float* out      = (float*)d_out;
    const int E     = in_sizes[5];

    zero_counts_kernel<<<(N_NODES + 255) / 256, 256>>>();
    degree_kernel<<<(E + 255) / 256, 256>>>(src, dst, E);
    // CSR build
    scan1_kernel<<<NB_SCAN, 1024>>>();
    scan2_kernel<<<1, 32>>>();
    scan3_kernel<<<(N_NODES + 255) / 256, 256>>>();
    scatter_kernel<<<(E + 255) / 256, 256>>>(src, dst, E);
    // Layer 1
    gemm1_kernel<<<(N_NODES + G1_BM - 1) / G1_BM, 128>>>(h, W1);
    spmm1_csr_kernel<<<(N_NODES * 32 + 255) / 256, 256>>>(b1);
    // Layer 2
    gemm2_kernel<<<(N_NODES + 127) / 128, 128>>>(W2);
    spmm2_csr_kernel<<<(N_NODES * 32 + 255) / 256, 256>>>(out, b2);
}

// round 3
// speedup vs baseline: 1.6508x; 1.0197x over previous
#include <cuda_runtime.h>
#include <math.h>
#include <float.h>

#define N_NODES 100000
#define IN_DIM  256
#define HID     128
#define OUT_DIM 40
#define E_MAX   3200000
#define NB_SCAN ((N_NODES + 1023) / 1024)   // 98

typedef unsigned long long u64;

// ---------------- scratch (device globals, allocation-free) ----------------
__device__ int   g_cnt_in[N_NODES];
__device__ int   g_cnt_out[N_NODES];
__device__ int   g_incl[N_NODES];
__device__ int   g_bsum[NB_SCAN];
__device__ int   g_boff[NB_SCAN];
__device__ int   g_row_off[N_NODES + 1];
__device__ int   g_cursor[N_NODES];
__device__ int   g_csr_src[E_MAX];
__device__ float g_buf1[(size_t)N_NODES * HID];  // h1 ; later x2 (stride 40)
__device__ float g_buf2[(size_t)N_NODES * HID];  // x1

// ---------------- packed fp32x2 helpers (Blackwell FFMA2) ----------------
__device__ __forceinline__ u64 ffma2(u64 a, u64 b, u64 c) {
    u64 d;
    asm("fma.rn.f32x2 %0, %1, %2, %3;" : "=l"(d) : "l"(a), "l"(b), "l"(c));
    return d;
}
__device__ __forceinline__ u64 dup2(float v) {
    unsigned int b = __float_as_uint(v);
    return ((u64)b << 32) | (u64)b;
}
__device__ __forceinline__ float lo2(u64 v) { return __uint_as_float((unsigned int)v); }
__device__ __forceinline__ float hi2(u64 v) { return __uint_as_float((unsigned int)(v >> 32)); }

// ---------------------------------------------------------------------------
__global__ void zero_counts_kernel() {
    int i = blockIdx.x * blockDim.x + threadIdx.x;
    if (i < N_NODES) { g_cnt_in[i] = 0; g_cnt_out[i] = 0; }
}

__global__ void degree_kernel(const int* __restrict__ src, const int* __restrict__ dst, int E) {
    int i = blockIdx.x * blockDim.x + threadIdx.x;
    if (i >= E) return;
    atomicAdd(&g_cnt_out[src[i]], 1);
    atomicAdd(&g_cnt_in[dst[i]], 1);
}

// ---------------- CSR build ----------------
__global__ __launch_bounds__(1024) void scan1_kernel() {
    __shared__ int sh[1024];
    int i = blockIdx.x * 1024 + threadIdx.x;
    int v = (i < N_NODES) ? g_cnt_in[i] : 0;
    sh[threadIdx.x] = v;
    __syncthreads();
#pragma unroll
    for (int o = 1; o < 1024; o <<= 1) {
        int t = (threadIdx.x >= o) ? sh[threadIdx.x - o] : 0;
        __syncthreads();
        sh[threadIdx.x] += t;
        __syncthreads();
    }
    if (i < N_NODES) g_incl[i] = sh[threadIdx.x];
    if (threadIdx.x == 1023) g_bsum[blockIdx.x] = sh[1023];
}

__global__ __launch_bounds__(128) void scan2_kernel() {
    __shared__ int sh[128];
    int t = threadIdx.x;
    int v = (t < NB_SCAN) ? g_bsum[t] : 0;
    sh[t] = v;
    __syncthreads();
#pragma unroll
    for (int o = 1; o < 128; o <<= 1) {
        int u = (t >= o) ? sh[t - o] : 0;
        __syncthreads();
        sh[t] += u;
        __syncthreads();
    }
    if (t < NB_SCAN) g_boff[t] = sh[t] - v;   // exclusive
}

__global__ void scan3_kernel() {
    int i = blockIdx.x * blockDim.x + threadIdx.x;
    if (i >= N_NODES) return;
    int boff = g_boff[i >> 10];
    int excl = g_incl[i] - g_cnt_in[i] + boff;
    g_row_off[i] = excl;
    g_cursor[i]  = excl;
    if (i == N_NODES - 1) g_row_off[N_NODES] = g_incl[i] + boff;
}

__global__ void scatter_kernel(const int* __restrict__ src, const int* __restrict__ dst, int E) {
    int e = blockIdx.x * blockDim.x + threadIdx.x;
    if (e >= E) return;
    int d = dst[e];
    int pos = atomicAdd(&g_cursor[d], 1);
    g_csr_src[pos] = src[e];
}

// ---------------------------------------------------------------------------
// GEMM1 (FFMA2): g_buf1 = (h @ W1) * rsqrt(max(deg_out,1))
// 64x128 tile, BK=16, 128 threads, per-thread 8(M) x 8(N) via 8x4 f32x2 acc.
// A tile stored pre-duplicated as f32x2 pairs; row padded (+1 u64) -> no bank
// conflicts on stores or loads.
// ---------------------------------------------------------------------------
#define G1_BM 64
#define G1_BK 16
__global__ __launch_bounds__(128) void gemm1_kernel(const float* __restrict__ A,
                                                    const float* __restrict__ B) {
    __shared__ u64   As2[G1_BK][G1_BM + 1];   // duplicated pairs, 8.3KB
    __shared__ float Bs[G1_BK][HID];          // 8KB
    const int tid = threadIdx.x;
    const int row0 = blockIdx.x * G1_BM;
    const int tm0 = (tid >> 4) * 8;           // 0..56
    const int tn0 = (tid & 15) * 8;           // 0..120
    const int ar = tid >> 2, ac = tid & 3;    // A: 32 rows x 4 float4-chunks
    const int bk = tid >> 5, bc = tid & 31;   // B: 4 k-rows x 32 float4-chunks

    u64 acc[8][4];
#pragma unroll
    for (int i = 0; i < 8; i++)
#pragma unroll
        for (int j = 0; j < 4; j++) acc[i][j] = 0ull;

    for (int k0 = 0; k0 < IN_DIM; k0 += G1_BK) {
#pragma unroll
        for (int rr = 0; rr < 2; rr++) {
            int row = row0 + ar + rr * 32;
            float4 v = make_float4(0.f, 0.f, 0.f, 0.f);
            if (row < N_NODES)
                v = *reinterpret_cast<const float4*>(A + (size_t)row * IN_DIM + k0 + ac * 4);
            As2[ac * 4 + 0][ar + rr * 32] = dup2(v.x);
            As2[ac * 4 + 1][ar + rr * 32] = dup2(v.y);
            As2[ac * 4 + 2][ar + rr * 32] = dup2(v.z);
            As2[ac * 4 + 3][ar + rr * 32] = dup2(v.w);
        }
#pragma unroll
        for (int i = 0; i < 4; i++) {
            float4 v = *reinterpret_cast<const float4*>(B + (size_t)(k0 + bk + 4 * i) * HID + bc * 4);
            *reinterpret_cast<float4*>(&Bs[bk + 4 * i][bc * 4]) = v;
        }
        __syncthreads();
#pragma unroll
        for (int k = 0; k < G1_BK; k++) {
            u64 ra[8];
#pragma unroll
            for (int i = 0; i < 8; i++) ra[i] = As2[k][tm0 + i];
            ulonglong2 t0 = *reinterpret_cast<const ulonglong2*>(&Bs[k][tn0]);
            ulonglong2 t1 = *reinterpret_cast<const ulonglong2*>(&Bs[k][tn0 + 4]);
            u64 rb[4] = {t0.x, t0.y, t1.x, t1.y};
#pragma unroll
            for (int i = 0; i < 8; i++)
#pragma unroll
                for (int j = 0; j < 4; j++) acc[i][j] = ffma2(ra[i], rb[j], acc[i][j]);
        }
        __syncthreads();
    }

#pragma unroll
    for (int i = 0; i < 8; i++) {
        int row = row0 + tm0 + i;
        if (row >= N_NODES) break;
        float s = rsqrtf(fmaxf((float)g_cnt_out[row], 1.0f));
        float4 v0 = make_float4(lo2(acc[i][0]) * s, hi2(acc[i][0]) * s,
                                lo2(acc[i][1]) * s, hi2(acc[i][1]) * s);
        float4 v1 = make_float4(lo2(acc[i][2]) * s, hi2(acc[i][2]) * s,
                                lo2(acc[i][3]) * s, hi2(acc[i][3]) * s);
        *reinterpret_cast<float4*>(g_buf1 + (size_t)row * HID + tn0)     = v0;
        *reinterpret_cast<float4*>(g_buf1 + (size_t)row * HID + tn0 + 4) = v1;
    }
}

// ---------------------------------------------------------------------------
// SpMM1 (pull, CSR): warp per dst node, fused norm+bias+relu.
// ---------------------------------------------------------------------------
__global__ __launch_bounds__(256) void spmm1_csr_kernel(const float* __restrict__ b1) {
    int n = (blockIdx.x * blockDim.x + threadIdx.x) >> 5;
    if (n >= N_NODES) return;
    int lane = threadIdx.x & 31;
    int start = g_row_off[n];
    int end   = g_row_off[n + 1];

    float ax = 0.f, ay = 0.f, az = 0.f, aw = 0.f;
    for (int j = start; j < end; j += 32) {
        int s = 0;
        if (j + lane < end) s = __ldg(&g_csr_src[j + lane]);
        int cnt = min(32, end - j);
        for (int k = 0; k < cnt; k++) {
            int sv = __shfl_sync(0xffffffff, s, k);
            float4 v = *reinterpret_cast<const float4*>(g_buf1 + (size_t)sv * HID + lane * 4);
            ax += v.x; ay += v.y; az += v.z; aw += v.w;
        }
    }

    float sc = rsqrtf(fmaxf((float)(end - start), 1.0f));
    float4 bb = *reinterpret_cast<const float4*>(b1 + lane * 4);
    float4 o;
    o.x = fmaxf(ax * sc + bb.x, 0.f);
    o.y = fmaxf(ay * sc + bb.y, 0.f);
    o.z = fmaxf(az * sc + bb.z, 0.f);
    o.w = fmaxf(aw * sc + bb.w, 0.f);
    *reinterpret_cast<float4*>(g_buf2 + (size_t)n * HID + lane * 4) = o;
}

// ---------------------------------------------------------------------------
// GEMM2 (FFMA2): g_buf1[:, :40] = (x1 @ W2) * rsqrt(max(deg_out,1))
// ---------------------------------------------------------------------------
__global__ __launch_bounds__(128) void gemm2_kernel(const float* __restrict__ W2) {
    __shared__ float Ws[HID * OUT_DIM];
    const int tid = threadIdx.x;
    for (int i = tid; i < HID * OUT_DIM; i += 128) Ws[i] = W2[i];
    __syncthreads();

    int row = blockIdx.x * 128 + tid;
    if (row >= N_NODES) return;

    u64 acc[OUT_DIM / 2];
#pragma unroll
    for (int c = 0; c < OUT_DIM / 2; c++) acc[c] = 0ull;

    const float* xr = g_buf2 + (size_t)row * HID;
#pragma unroll 4
    for (int k = 0; k < HID; k += 4) {
        float4 xv = *reinterpret_cast<const float4*>(xr + k);
        u64 xs0 = dup2(xv.x), xs1 = dup2(xv.y), xs2 = dup2(xv.z), xs3 = dup2(xv.w);
        const u64* w0 = reinterpret_cast<const u64*>(&Ws[(k + 0) * OUT_DIM]);
        const u64* w1 = reinterpret_cast<const u64*>(&Ws[(k + 1) * OUT_DIM]);
        const u64* w2 = reinterpret_cast<const u64*>(&Ws[(k + 2) * OUT_DIM]);
        const u64* w3 = reinterpret_cast<const u64*>(&Ws[(k + 3) * OUT_DIM]);
#pragma unroll
        for (int c = 0; c < OUT_DIM / 2; c++) {
            acc[c] = ffma2(xs0, w0[c], acc[c]);
            acc[c] = ffma2(xs1, w1[c], acc[c]);
            acc[c] = ffma2(xs2, w2[c], acc[c]);
            acc[c] = ffma2(xs3, w3[c], acc[c]);
        }
    }

    float s = rsqrtf(fmaxf((float)g_cnt_out[row], 1.0f));
    float* o = g_buf1 + (size_t)row * OUT_DIM;
#pragma unroll
    for (int c = 0; c < OUT_DIM / 2; c += 2) {
        float4 v = make_float4(lo2(acc[c]) * s, hi2(acc[c]) * s,
                               lo2(acc[c + 1]) * s, hi2(acc[c + 1]) * s);
        *reinterpret_cast<float4*>(o + 2 * c) = v;
    }
}

// ---------------------------------------------------------------------------
// SpMM2 (pull, CSR) + fused norm + bias + log_softmax.
// ---------------------------------------------------------------------------
__global__ __launch_bounds__(256) void spmm2_csr_kernel(float* __restrict__ out,
                                                        const float* __restrict__ b2) {
    int n = (blockIdx.x * blockDim.x + threadIdx.x) >> 5;
    if (n >= N_NODES) return;
    int lane = threadIdx.x & 31;
    bool act = lane < (OUT_DIM / 4);   // lanes 0..9
    int start = g_row_off[n];
    int end   = g_row_off[n + 1];

    float ax = 0.f, ay = 0.f, az = 0.f, aw = 0.f;
    for (int j = start; j < end; j += 32) {
        int s = 0;
        if (j + lane < end) s = __ldg(&g_csr_src[j + lane]);
        int cnt = min(32, end - j);
        for (int k = 0; k < cnt; k++) {
            int sv = __shfl_sync(0xffffffff, s, k);
            if (act) {
                float4 v = *reinterpret_cast<const float4*>(g_buf1 + (size_t)sv * OUT_DIM + lane * 4);
                ax += v.x; ay += v.y; az += v.z; aw += v.w;
            }
        }
    }

    float sc = rsqrtf(fmaxf((float)(end - start), 1.0f));
    float4 x = make_float4(-FLT_MAX, -FLT_MAX, -FLT_MAX, -FLT_MAX);
    if (act) {
        float4 bb = *reinterpret_cast<const float4*>(b2 + lane * 4);
        x.x = ax * sc + bb.x;
        x.y = ay * sc + bb.y;
        x.z = az * sc + bb.z;
        x.w = aw * sc + bb.w;
    }

    float m = fmaxf(fmaxf(x.x, x.y), fmaxf(x.z, x.w));
#pragma unroll
    for (int o = 16; o > 0; o >>= 1) m = fmaxf(m, __shfl_xor_sync(0xffffffff, m, o));

    float se = 0.f;
    if (act) se = expf(x.x - m) + expf(x.y - m) + expf(x.z - m) + expf(x.w - m);
#pragma unroll
    for (int o = 16; o > 0; o >>= 1) se += __shfl_xor_sync(0xffffffff, se, o);

    float lse = m + logf(se);
    if (act) {
        float4 r = make_float4(x.x - lse, x.y - lse, x.z - lse, x.w - lse);
        *reinterpret_cast<float4*>(out + (size_t)n * OUT_DIM + lane * 4) = r;
    }
}

// ---------------------------------------------------------------------------
extern "C" void kernel_launch(void* const* d_in, const int* in_sizes, int n_in,
                              void* d_out, int out_size) {
    const float* h  = (const float*)d_in[0];
    const float* W1 = (const float*)d_in[1];
    const float* b1 = (const float*)d_in[2];
    const float* W2 = (const float*)d_in[3];
    const float* b2 = (const float*)d_in[4];
    const int* src  = (const int*)d_in[5];
    const int* dst  = (const int*)d_in[6];
    float* out      = (float*)d_out;
    const int E     = in_sizes[5];

    zero_counts_kernel<<<(N_NODES + 255) / 256, 256>>>();
    degree_kernel<<<(E + 255) / 256, 256>>>(src, dst, E);
    scan1_kernel<<<NB_SCAN, 1024>>>();
    scan2_kernel<<<1, 128>>>();
    scan3_kernel<<<(N_NODES + 255) / 256, 256>>>();
    scatter_kernel<<<(E + 255) / 256, 256>>>(src, dst, E);
    gemm1_kernel<<<(N_NODES + G1_BM - 1) / G1_BM, 128>>>(h, W1);
    spmm1_csr_kernel<<<(N_NODES * 32 + 255) / 256, 256>>>(b1);
    gemm2_kernel<<<(N_NODES + 127) / 128, 128>>>(W2);
    spmm2_csr_kernel<<<(N_NODES * 32 + 255) / 256, 256>>>(out, b2);
}

// round 5
// speedup vs baseline: 1.6835x; 1.0198x over previous
#include <cuda_runtime.h>
#include <math.h>
#include <float.h>
#include <stdint.h>

#define N_NODES 100000
#define IN_DIM  256
#define HID     128
#define OUT_DIM 40
#define E_MAX   3200000
#define NB_SCAN ((N_NODES + 1023) / 1024)   // 98

typedef unsigned long long u64;

// ---------------- scratch (device globals, allocation-free) ----------------
__device__ int   g_cnt_in[N_NODES];
__device__ int   g_cnt_out[N_NODES];
__device__ int   g_incl[N_NODES];
__device__ int   g_bsum[NB_SCAN];
__device__ int   g_boff[NB_SCAN];
__device__ int   g_row_off[N_NODES + 1];
__device__ int   g_cursor[N_NODES];
__device__ int   g_csr_src[E_MAX];
__device__ float g_buf1[(size_t)N_NODES * HID];  // h1 ; later x2 (stride 40)
__device__ float g_buf2[(size_t)N_NODES * HID];  // x1

// ---------------- packed fp32x2 helpers (Blackwell FFMA2) ----------------
__device__ __forceinline__ u64 ffma2(u64 a, u64 b, u64 c) {
    u64 d;
    asm("fma.rn.f32x2 %0, %1, %2, %3;" : "=l"(d) : "l"(a), "l"(b), "l"(c));
    return d;
}
__device__ __forceinline__ u64 dup2(float v) {
    unsigned int b = __float_as_uint(v);
    return ((u64)b << 32) | (u64)b;
}
__device__ __forceinline__ float lo2(u64 v) { return __uint_as_float((unsigned int)v); }
__device__ __forceinline__ float hi2(u64 v) { return __uint_as_float((unsigned int)(v >> 32)); }

// ---------------------------------------------------------------------------
__global__ void zero_counts_kernel() {
    int i = blockIdx.x * blockDim.x + threadIdx.x;
    if (i < N_NODES) { g_cnt_in[i] = 0; g_cnt_out[i] = 0; }
}

// 4 edges per thread, int4 loads
__global__ void degree_kernel(const int4* __restrict__ src4, const int4* __restrict__ dst4, int E4) {
    int i = blockIdx.x * blockDim.x + threadIdx.x;
    if (i >= E4) return;
    int4 s = src4[i], d = dst4[i];
    atomicAdd(&g_cnt_out[s.x], 1); atomicAdd(&g_cnt_out[s.y], 1);
    atomicAdd(&g_cnt_out[s.z], 1); atomicAdd(&g_cnt_out[s.w], 1);
    atomicAdd(&g_cnt_in[d.x], 1);  atomicAdd(&g_cnt_in[d.y], 1);
    atomicAdd(&g_cnt_in[d.z], 1);  atomicAdd(&g_cnt_in[d.w], 1);
}

// ---------------- CSR build (shfl scans) ----------------
__global__ __launch_bounds__(1024) void scan1_kernel() {
    __shared__ int wsum[32];
    int tid = threadIdx.x, lane = tid & 31, wid = tid >> 5;
    int i = blockIdx.x * 1024 + tid;
    int v = (i < N_NODES) ? g_cnt_in[i] : 0;
    int x = v;
#pragma unroll
    for (int o = 1; o < 32; o <<= 1) {
        int t = __shfl_up_sync(0xffffffff, x, o);
        if (lane >= o) x += t;
    }
    if (lane == 31) wsum[wid] = x;
    __syncthreads();
    if (wid == 0) {
        int w = wsum[lane];
#pragma unroll
        for (int o = 1; o < 32; o <<= 1) {
            int t = __shfl_up_sync(0xffffffff, w, o);
            if (lane >= o) w += t;
        }
        wsum[lane] = w;
    }
    __syncthreads();
    int base = (wid > 0) ? wsum[wid - 1] : 0;
    x += base;
    if (i < N_NODES) g_incl[i] = x;
    if (tid == 1023) g_bsum[blockIdx.x] = x;
}

__global__ __launch_bounds__(128) void scan2_kernel() {
    __shared__ int wsum[4];
    int tid = threadIdx.x, lane = tid & 31, wid = tid >> 5;
    int v = (tid < NB_SCAN) ? g_bsum[tid] : 0;
    int x = v;
#pragma unroll
    for (int o = 1; o < 32; o <<= 1) {
        int t = __shfl_up_sync(0xffffffff, x, o);
        if (lane >= o) x += t;
    }
    if (lane == 31) wsum[wid] = x;
    __syncthreads();
    int base = 0;
#pragma unroll
    for (int w = 0; w < 4; w++) base += (w < wid) ? wsum[w] : 0;
    if (tid < NB_SCAN) g_boff[tid] = x + base - v;   // exclusive
}

__global__ void scan3_kernel() {
    int i = blockIdx.x * blockDim.x + threadIdx.x;
    if (i >= N_NODES) return;
    int boff = g_boff[i >> 10];
    int excl = g_incl[i] - g_cnt_in[i] + boff;
    g_row_off[i] = excl;
    g_cursor[i]  = excl;
    if (i == N_NODES - 1) g_row_off[N_NODES] = g_incl[i] + boff;
}

__global__ void scatter_kernel(const int4* __restrict__ src4, const int4* __restrict__ dst4, int E4) {
    int i = blockIdx.x * blockDim.x + threadIdx.x;
    if (i >= E4) return;
    int4 s = src4[i], d = dst4[i];
    g_csr_src[atomicAdd(&g_cursor[d.x], 1)] = s.x;
    g_csr_src[atomicAdd(&g_cursor[d.y], 1)] = s.y;
    g_csr_src[atomicAdd(&g_cursor[d.z], 1)] = s.z;
    g_csr_src[atomicAdd(&g_cursor[d.w], 1)] = s.w;
}

// ---------------------------------------------------------------------------
// GEMM1 (FFMA2): g_buf1 = (h @ W1) * rsqrt(max(deg_out,1))
// 64x128 tile, BK=16, 128 threads, 8(M) x 8(N) per thread via 8x4 f32x2 acc.
// ---------------------------------------------------------------------------
#define G1_BM 64
#define G1_BK 16
__global__ __launch_bounds__(128) void gemm1_kernel(const float* __restrict__ A,
                                                    const float* __restrict__ B) {
    __shared__ u64   As2[G1_BK][G1_BM + 1];
    __shared__ float Bs[G1_BK][HID];
    const int tid = threadIdx.x;
    const int row0 = blockIdx.x * G1_BM;
    const int tm0 = (tid >> 4) * 8;
    const int tn0 = (tid & 15) * 8;
    const int ar = tid >> 2, ac = tid & 3;
    const int bk = tid >> 5, bc = tid & 31;

    u64 acc[8][4];
#pragma unroll
    for (int i = 0; i < 8; i++)
#pragma unroll
        for (int j = 0; j < 4; j++) acc[i][j] = 0ull;

    for (int k0 = 0; k0 < IN_DIM; k0 += G1_BK) {
#pragma unroll
        for (int rr = 0; rr < 2; rr++) {
            int row = row0 + ar + rr * 32;
            float4 v = make_float4(0.f, 0.f, 0.f, 0.f);
            if (row < N_NODES)
                v = *reinterpret_cast<const float4*>(A + (size_t)row * IN_DIM + k0 + ac * 4);
            As2[ac * 4 + 0][ar + rr * 32] = dup2(v.x);
            As2[ac * 4 + 1][ar + rr * 32] = dup2(v.y);
            As2[ac * 4 + 2][ar + rr * 32] = dup2(v.z);
            As2[ac * 4 + 3][ar + rr * 32] = dup2(v.w);
        }
#pragma unroll
        for (int i = 0; i < 4; i++) {
            float4 v = *reinterpret_cast<const float4*>(B + (size_t)(k0 + bk + 4 * i) * HID + bc * 4);
            *reinterpret_cast<float4*>(&Bs[bk + 4 * i][bc * 4]) = v;
        }
        __syncthreads();
#pragma unroll
        for (int k = 0; k < G1_BK; k++) {
            u64 ra[8];
#pragma unroll
            for (int i = 0; i < 8; i++) ra[i] = As2[k][tm0 + i];
            ulonglong2 t0 = *reinterpret_cast<const ulonglong2*>(&Bs[k][tn0]);
            ulonglong2 t1 = *reinterpret_cast<const ulonglong2*>(&Bs[k][tn0 + 4]);
            u64 rb[4] = {t0.x, t0.y, t1.x, t1.y};
#pragma unroll
            for (int i = 0; i < 8; i++)
#pragma unroll
                for (int j = 0; j < 4; j++) acc[i][j] = ffma2(ra[i], rb[j], acc[i][j]);
        }
        __syncthreads();
    }

#pragma unroll
    for (int i = 0; i < 8; i++) {
        int row = row0 + tm0 + i;
        if (row >= N_NODES) break;
        float s = rsqrtf(fmaxf((float)g_cnt_out[row], 1.0f));
        float4 v0 = make_float4(lo2(acc[i][0]) * s, hi2(acc[i][0]) * s,
                                lo2(acc[i][1]) * s, hi2(acc[i][1]) * s);
        float4 v1 = make_float4(lo2(acc[i][2]) * s, hi2(acc[i][2]) * s,
                                lo2(acc[i][3]) * s, hi2(acc[i][3]) * s);
        *reinterpret_cast<float4*>(g_buf1 + (size_t)row * HID + tn0)     = v0;
        *reinterpret_cast<float4*>(g_buf1 + (size_t)row * HID + tn0 + 4) = v1;
    }
}

// ---------------------------------------------------------------------------
// SpMM1 (pull, CSR): warp per dst node, fused norm+bias+relu.
// ---------------------------------------------------------------------------
__global__ __launch_bounds__(256) void spmm1_csr_kernel(const float* __restrict__ b1) {
    int n = (blockIdx.x * blockDim.x + threadIdx.x) >> 5;
    if (n >= N_NODES) return;
    int lane = threadIdx.x & 31;
    int start = g_row_off[n];
    int end   = g_row_off[n + 1];

    float ax = 0.f, ay = 0.f, az = 0.f, aw = 0.f;
    for (int j = start; j < end; j += 32) {
        int s = 0;
        if (j + lane < end) s = __ldg(&g_csr_src[j + lane]);
        int cnt = min(32, end - j);
        for (int k = 0; k < cnt; k++) {
            int sv = __shfl_sync(0xffffffff, s, k);
            float4 v = *reinterpret_cast<const float4*>(g_buf1 + (size_t)sv * HID + lane * 4);
            ax += v.x; ay += v.y; az += v.z; aw += v.w;
        }
    }

    float sc = rsqrtf(fmaxf((float)(end - start), 1.0f));
    float4 bb = *reinterpret_cast<const float4*>(b1 + lane * 4);
    float4 o;
    o.x = fmaxf(ax * sc + bb.x, 0.f);
    o.y = fmaxf(ay * sc + bb.y, 0.f);
    o.z = fmaxf(az * sc + bb.z, 0.f);
    o.w = fmaxf(aw * sc + bb.w, 0.f);
    *reinterpret_cast<float4*>(g_buf2 + (size_t)n * HID + lane * 4) = o;
}

// ---------------------------------------------------------------------------
// GEMM2 (FFMA2): g_buf1[:, :40] = (x1 @ W2) * rsqrt(max(deg_out,1))
// ---------------------------------------------------------------------------
__global__ __launch_bounds__(128) void gemm2_kernel(const float* __restrict__ W2) {
    __shared__ float Ws[HID * OUT_DIM];
    const int tid = threadIdx.x;
    for (int i = tid; i < HID * OUT_DIM; i += 128) Ws[i] = W2[i];
    __syncthreads();

    int row = blockIdx.x * 128 + tid;
    if (row >= N_NODES) return;

    u64 acc[OUT_DIM / 2];
#pragma unroll
    for (int c = 0; c < OUT_DIM / 2; c++) acc[c] = 0ull;

    const float* xr = g_buf2 + (size_t)row * HID;
#pragma unroll 4
    for (int k = 0; k < HID; k += 4) {
        float4 xv = *reinterpret_cast<const float4*>(xr + k);
        u64 xs0 = dup2(xv.x), xs1 = dup2(xv.y), xs2 = dup2(xv.z), xs3 = dup2(xv.w);
        const u64* w0 = reinterpret_cast<const u64*>(&Ws[(k + 0) * OUT_DIM]);
        const u64* w1 = reinterpret_cast<const u64*>(&Ws[(k + 1) * OUT_DIM]);
        const u64* w2 = reinterpret_cast<const u64*>(&Ws[(k + 2) * OUT_DIM]);
        const u64* w3 = reinterpret_cast<const u64*>(&Ws[(k + 3) * OUT_DIM]);
#pragma unroll
        for (int c = 0; c < OUT_DIM / 2; c++) {
            acc[c] = ffma2(xs0, w0[c], acc[c]);
            acc[c] = ffma2(xs1, w1[c], acc[c]);
            acc[c] = ffma2(xs2, w2[c], acc[c]);
            acc[c] = ffma2(xs3, w3[c], acc[c]);
        }
    }

    float s = rsqrtf(fmaxf((float)g_cnt_out[row], 1.0f));
    float* o = g_buf1 + (size_t)row * OUT_DIM;
#pragma unroll
    for (int c = 0; c < OUT_DIM / 2; c += 2) {
        float4 v = make_float4(lo2(acc[c]) * s, hi2(acc[c]) * s,
                               lo2(acc[c + 1]) * s, hi2(acc[c + 1]) * s);
        *reinterpret_cast<float4*>(o + 2 * c) = v;
    }
}

// ---------------------------------------------------------------------------
// SpMM2 (pull, CSR) + fused norm + bias + log_softmax.
// Dual-edge per iteration: lanes 0..9 handle edge k, lanes 16..25 edge k+1.
// ---------------------------------------------------------------------------
__global__ __launch_bounds__(256) void spmm2_csr_kernel(float* __restrict__ out,
                                                        const float* __restrict__ b2) {
    int n = (blockIdx.x * blockDim.x + threadIdx.x) >> 5;
    if (n >= N_NODES) return;
    int lane = threadIdx.x & 31;
    int half = lane >> 4;              // 0 or 1
    int hl   = lane & 15;              // lane within half
    bool act = hl < (OUT_DIM / 4);     // chunks 0..9 per half
    int start = g_row_off[n];
    int end   = g_row_off[n + 1];

    float ax = 0.f, ay = 0.f, az = 0.f, aw = 0.f;
    for (int j = start; j < end; j += 32) {
        int s = 0;
        if (j + lane < end) s = __ldg(&g_csr_src[j + lane]);
        int cnt = min(32, end - j);
        for (int k = 0; k < cnt; k += 2) {
            int idx = k + half;                    // half 0 -> k, half 1 -> k+1
            bool ok = act && (idx < cnt);
            int sv = __shfl_sync(0xffffffff, s, idx < cnt ? idx : k);
            if (ok) {
                float4 v = *reinterpret_cast<const float4*>(g_buf1 + (size_t)sv * OUT_DIM + hl * 4);
                ax += v.x; ay += v.y; az += v.z; aw += v.w;
            }
        }
    }
    // combine halves into lanes 0..9
    ax += __shfl_down_sync(0xffffffff, ax, 16);
    ay += __shfl_down_sync(0xffffffff, ay, 16);
    az += __shfl_down_sync(0xffffffff, az, 16);
    aw += __shfl_down_sync(0xffffffff, aw, 16);

    bool fin = (lane < OUT_DIM / 4);
    float sc = rsqrtf(fmaxf((float)(end - start), 1.0f));
    float4 x = make_float4(-FLT_MAX, -FLT_MAX, -FLT_MAX, -FLT_MAX);
    if (fin) {
        float4 bb = *reinterpret_cast<const float4*>(b2 + lane * 4);
        x.x = ax * sc + bb.x;
        x.y = ay * sc + bb.y;
        x.z = az * sc + bb.z;
        x.w = aw * sc + bb.w;
    }

    float m = fmaxf(fmaxf(x.x, x.y), fmaxf(x.z, x.w));
#pragma unroll
    for (int o = 16; o > 0; o >>= 1) m = fmaxf(m, __shfl_xor_sync(0xffffffff, m, o));

    float se = 0.f;
    if (fin) se = expf(x.x - m) + expf(x.y - m) + expf(x.z - m) + expf(x.w - m);
#pragma unroll
    for (int o = 16; o > 0; o >>= 1) se += __shfl_xor_sync(0xffffffff, se, o);

    float lse = m + logf(se);
    if (fin) {
        float4 r = make_float4(x.x - lse, x.y - lse, x.z - lse, x.w - lse);
        *reinterpret_cast<float4*>(out + (size_t)n * OUT_DIM + lane * 4) = r;
    }
}

// ---------------------------------------------------------------------------
extern "C" void kernel_launch(void* const* d_in, const int* in_sizes, int n_in,
                              void* d_out, int out_size) {
    const float* h  = (const float*)d_in[0];
    const float* W1 = (const float*)d_in[1];
    const float* b1 = (const float*)d_in[2];
    const float* W2 = (const float*)d_in[3];
    const float* b2 = (const float*)d_in[4];
    const int* src  = (const int*)d_in[5];
    const int* dst  = (const int*)d_in[6];
    float* out      = (float*)d_out;
    const int E     = in_sizes[5];
    const int E4    = E / 4;   // E = 3.2M, divisible by 4

    zero_counts_kernel<<<(N_NODES + 255) / 256, 256>>>();                                    // 1
    degree_kernel<<<(E4 + 255) / 256, 256>>>((const int4*)src, (const int4*)dst, E4);        // 2
    scan1_kernel<<<NB_SCAN, 1024>>>();                                                       // 3
    gemm1_kernel<<<(N_NODES + G1_BM - 1) / G1_BM, 128>>>(h, W1);                             // 4 (profiled)
    scan2_kernel<<<1, 128>>>();                                                              // 5
    scan3_kernel<<<(N_NODES + 255) / 256, 256>>>();                                          // 6
    scatter_kernel<<<(E4 + 255) / 256, 256>>>((const int4*)src, (const int4*)dst, E4);       // 7
    spmm1_csr_kernel<<<(N_NODES * 32 + 255) / 256, 256>>>(b1);                               // 8
    gemm2_kernel<<<(N_NODES + 127) / 128, 128>>>(W2);                                        // 9
    spmm2_csr_kernel<<<(N_NODES * 32 + 255) / 256, 256>>>(out, b2);                          // 10
}

// round 6
// speedup vs baseline: 1.7154x; 1.0189x over previous
#include <cuda_runtime.h>
#include <math.h>
#include <float.h>
#include <stdint.h>

#define N_NODES 100000
#define IN_DIM  256
#define HID     128
#define OUT_DIM 40
#define E_MAX   3200000
#define NB_SCAN ((N_NODES + 1023) / 1024)   // 98

typedef unsigned long long u64;

// ---------------- scratch (device globals, allocation-free) ----------------
__device__ int   g_cnt_in[N_NODES];
__device__ int   g_cnt_out[N_NODES];
__device__ int   g_incl[N_NODES];
__device__ int   g_bsum[NB_SCAN];
__device__ int   g_boff[NB_SCAN];
__device__ int   g_row_off[N_NODES + 1];
__device__ int   g_cursor[N_NODES];
__device__ int   g_csr_src[E_MAX];
__device__ float g_buf1[(size_t)N_NODES * HID];  // h1 ; later x2 (stride 40)
__device__ float g_buf2[(size_t)N_NODES * HID];  // x1

// ---------------- packed fp32x2 helpers (Blackwell FFMA2) ----------------
__device__ __forceinline__ u64 ffma2(u64 a, u64 b, u64 c) {
    u64 d;
    asm("fma.rn.f32x2 %0, %1, %2, %3;" : "=l"(d) : "l"(a), "l"(b), "l"(c));
    return d;
}
__device__ __forceinline__ u64 dup2(float v) {
    unsigned int b = __float_as_uint(v);
    return ((u64)b << 32) | (u64)b;
}
__device__ __forceinline__ float lo2(u64 v) { return __uint_as_float((unsigned int)v); }
__device__ __forceinline__ float hi2(u64 v) { return __uint_as_float((unsigned int)(v >> 32)); }

__device__ __forceinline__ uint32_t smem_u32(const void* p) {
    uint32_t a;
    asm("{ .reg .u64 t; cvta.to.shared.u64 t, %1; cvt.u32.u64 %0, t; }" : "=r"(a) : "l"(p));
    return a;
}
__device__ __forceinline__ void cp_async16(uint32_t smem_dst, const void* gmem_src) {
    asm volatile("cp.async.ca.shared.global [%0], [%1], 16;" :: "r"(smem_dst), "l"(gmem_src) : "memory");
}
__device__ __forceinline__ void cp_commit() {
    asm volatile("cp.async.commit_group;" ::: "memory");
}
template <int N>
__device__ __forceinline__ void cp_wait() {
    asm volatile("cp.async.wait_group %0;" :: "n"(N) : "memory");
}

// ---------------------------------------------------------------------------
__global__ void zero_counts_kernel() {
    int i = blockIdx.x * blockDim.x + threadIdx.x;
    if (i < N_NODES) { g_cnt_in[i] = 0; g_cnt_out[i] = 0; }
}

__global__ void degree_kernel(const int4* __restrict__ src4, const int4* __restrict__ dst4, int E4) {
    int i = blockIdx.x * blockDim.x + threadIdx.x;
    if (i >= E4) return;
    int4 s = src4[i], d = dst4[i];
    atomicAdd(&g_cnt_out[s.x], 1); atomicAdd(&g_cnt_out[s.y], 1);
    atomicAdd(&g_cnt_out[s.z], 1); atomicAdd(&g_cnt_out[s.w], 1);
    atomicAdd(&g_cnt_in[d.x], 1);  atomicAdd(&g_cnt_in[d.y], 1);
    atomicAdd(&g_cnt_in[d.z], 1);  atomicAdd(&g_cnt_in[d.w], 1);
}

// ---------------- CSR build (shfl scans) ----------------
__global__ __launch_bounds__(1024) void scan1_kernel() {
    __shared__ int wsum[32];
    int tid = threadIdx.x, lane = tid & 31, wid = tid >> 5;
    int i = blockIdx.x * 1024 + tid;
    int v = (i < N_NODES) ? g_cnt_in[i] : 0;
    int x = v;
#pragma unroll
    for (int o = 1; o < 32; o <<= 1) {
        int t = __shfl_up_sync(0xffffffff, x, o);
        if (lane >= o) x += t;
    }
    if (lane == 31) wsum[wid] = x;
    __syncthreads();
    if (wid == 0) {
        int w = wsum[lane];
#pragma unroll
        for (int o = 1; o < 32; o <<= 1) {
            int t = __shfl_up_sync(0xffffffff, w, o);
            if (lane >= o) w += t;
        }
        wsum[lane] = w;
    }
    __syncthreads();
    int base = (wid > 0) ? wsum[wid - 1] : 0;
    x += base;
    if (i < N_NODES) g_incl[i] = x;
    if (tid == 1023) g_bsum[blockIdx.x] = x;
}

__global__ __launch_bounds__(128) void scan2_kernel() {
    __shared__ int wsum[4];
    int tid = threadIdx.x, lane = tid & 31, wid = tid >> 5;
    int v = (tid < NB_SCAN) ? g_bsum[tid] : 0;
    int x = v;
#pragma unroll
    for (int o = 1; o < 32; o <<= 1) {
        int t = __shfl_up_sync(0xffffffff, x, o);
        if (lane >= o) x += t;
    }
    if (lane == 31) wsum[wid] = x;
    __syncthreads();
    int base = 0;
#pragma unroll
    for (int w = 0; w < 4; w++) base += (w < wid) ? wsum[w] : 0;
    if (tid < NB_SCAN) g_boff[tid] = x + base - v;   // exclusive
}

__global__ void scan3_kernel() {
    int i = blockIdx.x * blockDim.x + threadIdx.x;
    if (i >= N_NODES) return;
    int boff = g_boff[i >> 10];
    int excl = g_incl[i] - g_cnt_in[i] + boff;
    g_row_off[i] = excl;
    g_cursor[i]  = excl;
    if (i == N_NODES - 1) g_row_off[N_NODES] = g_incl[i] + boff;
}

__global__ void scatter_kernel(const int4* __restrict__ src4, const int4* __restrict__ dst4, int E4) {
    int i = blockIdx.x * blockDim.x + threadIdx.x;
    if (i >= E4) return;
    int4 s = src4[i], d = dst4[i];
    g_csr_src[atomicAdd(&g_cursor[d.x], 1)] = s.x;
    g_csr_src[atomicAdd(&g_cursor[d.y], 1)] = s.y;
    g_csr_src[atomicAdd(&g_cursor[d.z], 1)] = s.z;
    g_csr_src[atomicAdd(&g_cursor[d.w], 1)] = s.w;
}

// ---------------------------------------------------------------------------
// GEMM1 (FFMA2, cp.async double-buffered): g_buf1 = (h @ W1) * deg_out^-1/2
// BM=64, BN=128, BK=16, 128 threads, 8x8 per thread (8x4 f32x2 acc).
// One __syncthreads per k-tile; B staged via cp.async; A prefetched in regs.
// ---------------------------------------------------------------------------
#define G1_BM 64
#define G1_BK 16
#define G1_NIT (IN_DIM / G1_BK)   // 16
__global__ __launch_bounds__(128, 4) void gemm1_kernel(const float* __restrict__ A,
                                                       const float* __restrict__ B) {
    __shared__ u64   As2[2][G1_BK][G1_BM + 1];   // duplicated pairs, 16.6KB
    __shared__ float Bs[2][G1_BK][HID];          // 16KB
    const int tid = threadIdx.x;
    const int row0 = blockIdx.x * G1_BM;
    const int tm0 = (tid >> 4) * 8;
    const int tn0 = (tid & 15) * 8;
    const int ar = tid >> 2, ac = tid & 3;   // A: rows ar, ar+32; float4 chunk ac
    const int br = tid >> 5, bc = tid & 31;  // B: rows br+4i; 16B chunk bc

    const int rowA0 = row0 + ar, rowA1 = row0 + ar + 32;
    const float* pA0 = A + (size_t)rowA0 * IN_DIM + ac * 4;
    const float* pA1 = A + (size_t)rowA1 * IN_DIM + ac * 4;
    const bool okA0 = rowA0 < N_NODES, okA1 = rowA1 < N_NODES;

    u64 acc[8][4];
#pragma unroll
    for (int i = 0; i < 8; i++)
#pragma unroll
        for (int j = 0; j < 4; j++) acc[i][j] = 0ull;

    float4 pa0, pa1;
    const float4 z4 = make_float4(0.f, 0.f, 0.f, 0.f);

    // ---- prologue: stage tile 0 into buffer 0 ----
    pa0 = okA0 ? *reinterpret_cast<const float4*>(pA0) : z4;
    pa1 = okA1 ? *reinterpret_cast<const float4*>(pA1) : z4;
    As2[0][ac * 4 + 0][ar] = dup2(pa0.x);
    As2[0][ac * 4 + 1][ar] = dup2(pa0.y);
    As2[0][ac * 4 + 2][ar] = dup2(pa0.z);
    As2[0][ac * 4 + 3][ar] = dup2(pa0.w);
    As2[0][ac * 4 + 0][ar + 32] = dup2(pa1.x);
    As2[0][ac * 4 + 1][ar + 32] = dup2(pa1.y);
    As2[0][ac * 4 + 2][ar + 32] = dup2(pa1.z);
    As2[0][ac * 4 + 3][ar + 32] = dup2(pa1.w);
#pragma unroll
    for (int i = 0; i < 4; i++)
        cp_async16(smem_u32(&Bs[0][br + 4 * i][bc * 4]), B + (size_t)(br + 4 * i) * HID + bc * 4);
    cp_commit();

    int cur = 0;
    for (int it = 0; it < G1_NIT; it++) {
        const bool more = (it + 1 < G1_NIT);
        if (more) {
            const int k1 = (it + 1) * G1_BK;
            pa0 = okA0 ? *reinterpret_cast<const float4*>(pA0 + k1) : z4;
            pa1 = okA1 ? *reinterpret_cast<const float4*>(pA1 + k1) : z4;
#pragma unroll
            for (int i = 0; i < 4; i++)
                cp_async16(smem_u32(&Bs[cur ^ 1][br + 4 * i][bc * 4]),
                           B + (size_t)(k1 + br + 4 * i) * HID + bc * 4);
            cp_commit();
            cp_wait<1>();
        } else {
            cp_wait<0>();
        }
        __syncthreads();

#pragma unroll
        for (int k = 0; k < G1_BK; k++) {
            u64 ra[8];
#pragma unroll
            for (int i = 0; i < 8; i++) ra[i] = As2[cur][k][tm0 + i];
            ulonglong2 t0 = *reinterpret_cast<const ulonglong2*>(&Bs[cur][k][tn0]);
            ulonglong2 t1 = *reinterpret_cast<const ulonglong2*>(&Bs[cur][k][tn0 + 4]);
            u64 rb[4] = {t0.x, t0.y, t1.x, t1.y};
#pragma unroll
            for (int i = 0; i < 8; i++)
#pragma unroll
                for (int j = 0; j < 4; j++) acc[i][j] = ffma2(ra[i], rb[j], acc[i][j]);
        }

        if (more) {
            const int nb = cur ^ 1;
            As2[nb][ac * 4 + 0][ar] = dup2(pa0.x);
            As2[nb][ac * 4 + 1][ar] = dup2(pa0.y);
            As2[nb][ac * 4 + 2][ar] = dup2(pa0.z);
            As2[nb][ac * 4 + 3][ar] = dup2(pa0.w);
            As2[nb][ac * 4 + 0][ar + 32] = dup2(pa1.x);
            As2[nb][ac * 4 + 1][ar + 32] = dup2(pa1.y);
            As2[nb][ac * 4 + 2][ar + 32] = dup2(pa1.z);
            As2[nb][ac * 4 + 3][ar + 32] = dup2(pa1.w);
        }
        cur ^= 1;
    }

#pragma unroll
    for (int i = 0; i < 8; i++) {
        int row = row0 + tm0 + i;
        if (row >= N_NODES) break;
        float s = rsqrtf(fmaxf((float)g_cnt_out[row], 1.0f));
        float4 v0 = make_float4(lo2(acc[i][0]) * s, hi2(acc[i][0]) * s,
                                lo2(acc[i][1]) * s, hi2(acc[i][1]) * s);
        float4 v1 = make_float4(lo2(acc[i][2]) * s, hi2(acc[i][2]) * s,
                                lo2(acc[i][3]) * s, hi2(acc[i][3]) * s);
        *reinterpret_cast<float4*>(g_buf1 + (size_t)row * HID + tn0)     = v0;
        *reinterpret_cast<float4*>(g_buf1 + (size_t)row * HID + tn0 + 4) = v1;
    }
}

// ---------------------------------------------------------------------------
// SpMM1 (pull, CSR): warp per dst node, fused norm+bias+relu.
// ---------------------------------------------------------------------------
__global__ __launch_bounds__(256) void spmm1_csr_kernel(const float* __restrict__ b1) {
    int n = (blockIdx.x * blockDim.x + threadIdx.x) >> 5;
    if (n >= N_NODES) return;
    int lane = threadIdx.x & 31;
    int start = g_row_off[n];
    int end   = g_row_off[n + 1];

    float ax = 0.f, ay = 0.f, az = 0.f, aw = 0.f;
    for (int j = start; j < end; j += 32) {
        int s = 0;
        if (j + lane < end) s = __ldg(&g_csr_src[j + lane]);
        int cnt = min(32, end - j);
        for (int k = 0; k < cnt; k++) {
            int sv = __shfl_sync(0xffffffff, s, k);
            float4 v = *reinterpret_cast<const float4*>(g_buf1 + (size_t)sv * HID + lane * 4);
            ax += v.x; ay += v.y; az += v.z; aw += v.w;
        }
    }

    float sc = rsqrtf(fmaxf((float)(end - start), 1.0f));
    float4 bb = *reinterpret_cast<const float4*>(b1 + lane * 4);
    float4 o;
    o.x = fmaxf(ax * sc + bb.x, 0.f);
    o.y = fmaxf(ay * sc + bb.y, 0.f);
    o.z = fmaxf(az * sc + bb.z, 0.f);
    o.w = fmaxf(aw * sc + bb.w, 0.f);
    *reinterpret_cast<float4*>(g_buf2 + (size_t)n * HID + lane * 4) = o;
}

// ---------------------------------------------------------------------------
// GEMM2 (FFMA2): g_buf1[:, :40] = (x1 @ W2) * rsqrt(max(deg_out,1))
// ---------------------------------------------------------------------------
__global__ __launch_bounds__(128) void gemm2_kernel(const float* __restrict__ W2) {
    __shared__ float Ws[HID * OUT_DIM];
    const int tid = threadIdx.x;
    for (int i = tid; i < HID * OUT_DIM; i += 128) Ws[i] = W2[i];
    __syncthreads();

    int row = blockIdx.x * 128 + tid;
    if (row >= N_NODES) return;

    u64 acc[OUT_DIM / 2];
#pragma unroll
    for (int c = 0; c < OUT_DIM / 2; c++) acc[c] = 0ull;

    const float* xr = g_buf2 + (size_t)row * HID;
#pragma unroll 4
    for (int k = 0; k < HID; k += 4) {
        float4 xv = *reinterpret_cast<const float4*>(xr + k);
        u64 xs0 = dup2(xv.x), xs1 = dup2(xv.y), xs2 = dup2(xv.z), xs3 = dup2(xv.w);
        const u64* w0 = reinterpret_cast<const u64*>(&Ws[(k + 0) * OUT_DIM]);
        const u64* w1 = reinterpret_cast<const u64*>(&Ws[(k + 1) * OUT_DIM]);
        const u64* w2 = reinterpret_cast<const u64*>(&Ws[(k + 2) * OUT_DIM]);
        const u64* w3 = reinterpret_cast<const u64*>(&Ws[(k + 3) * OUT_DIM]);
#pragma unroll
        for (int c = 0; c < OUT_DIM / 2; c++) {
            acc[c] = ffma2(xs0, w0[c], acc[c]);
            acc[c] = ffma2(xs1, w1[c], acc[c]);
            acc[c] = ffma2(xs2, w2[c], acc[c]);
            acc[c] = ffma2(xs3, w3[c], acc[c]);
        }
    }

    float s = rsqrtf(fmaxf((float)g_cnt_out[row], 1.0f));
    float* o = g_buf1 + (size_t)row * OUT_DIM;
#pragma unroll
    for (int c = 0; c < OUT_DIM / 2; c += 2) {
        float4 v = make_float4(lo2(acc[c]) * s, hi2(acc[c]) * s,
                               lo2(acc[c + 1]) * s, hi2(acc[c + 1]) * s);
        *reinterpret_cast<float4*>(o + 2 * c) = v;
    }
}

// ---------------------------------------------------------------------------
// SpMM2 (pull, CSR) + fused norm + bias + log_softmax. Dual-edge per iter.
// ---------------------------------------------------------------------------
__global__ __launch_bounds__(256) void spmm2_csr_kernel(float* __restrict__ out,
                                                        const float* __restrict__ b2) {
    int n = (blockIdx.x * blockDim.x + threadIdx.x) >> 5;
    if (n >= N_NODES) return;
    int lane = threadIdx.x & 31;
    int half = lane >> 4;
    int hl   = lane & 15;
    bool act = hl < (OUT_DIM / 4);
    int start = g_row_off[n];
    int end   = g_row_off[n + 1];

    float ax = 0.f, ay = 0.f, az = 0.f, aw = 0.f;
    for (int j = start; j < end; j += 32) {
        int s = 0;
        if (j + lane < end) s = __ldg(&g_csr_src[j + lane]);
        int cnt = min(32, end - j);
        for (int k = 0; k < cnt; k += 2) {
            int idx = k + half;
            bool ok = act && (idx < cnt);
            int sv = __shfl_sync(0xffffffff, s, idx < cnt ? idx : k);
            if (ok) {
                float4 v = *reinterpret_cast<const float4*>(g_buf1 + (size_t)sv * OUT_DIM + hl * 4);
                ax += v.x; ay += v.y; az += v.z; aw += v.w;
            }
        }
    }
    ax += __shfl_down_sync(0xffffffff, ax, 16);
    ay += __shfl_down_sync(0xffffffff, ay, 16);
    az += __shfl_down_sync(0xffffffff, az, 16);
    aw += __shfl_down_sync(0xffffffff, aw, 16);

    bool fin = (lane < OUT_DIM / 4);
    float sc = rsqrtf(fmaxf((float)(end - start), 1.0f));
    float4 x = make_float4(-FLT_MAX, -FLT_MAX, -FLT_MAX, -FLT_MAX);
    if (fin) {
        float4 bb = *reinterpret_cast<const float4*>(b2 + lane * 4);
        x.x = ax * sc + bb.x;
        x.y = ay * sc + bb.y;
        x.z = az * sc + bb.z;
        x.w = aw * sc + bb.w;
    }

    float m = fmaxf(fmaxf(x.x, x.y), fmaxf(x.z, x.w));
#pragma unroll
    for (int o = 16; o > 0; o >>= 1) m = fmaxf(m, __shfl_xor_sync(0xffffffff, m, o));

    float se = 0.f;
    if (fin) se = expf(x.x - m) + expf(x.y - m) + expf(x.z - m) + expf(x.w - m);
#pragma unroll
    for (int o = 16; o > 0; o >>= 1) se += __shfl_xor_sync(0xffffffff, se, o);

    float lse = m + logf(se);
    if (fin) {
        float4 r = make_float4(x.x - lse, x.y - lse, x.z - lse, x.w - lse);
        *reinterpret_cast<float4*>(out + (size_t)n * OUT_DIM + lane * 4) = r;
    }
}

// ---------------------------------------------------------------------------
extern "C" void kernel_launch(void* const* d_in, const int* in_sizes, int n_in,
                              void* d_out, int out_size) {
    const float* h  = (const float*)d_in[0];
    const float* W1 = (const float*)d_in[1];
    const float* b1 = (const float*)d_in[2];
    const float* W2 = (const float*)d_in[3];
    const float* b2 = (const float*)d_in[4];
    const int* src  = (const int*)d_in[5];
    const int* dst  = (const int*)d_in[6];
    float* out      = (float*)d_out;
    const int E     = in_sizes[5];
    const int E4    = E / 4;

    zero_counts_kernel<<<(N_NODES + 255) / 256, 256>>>();                                    // 1
    degree_kernel<<<(E4 + 255) / 256, 256>>>((const int4*)src, (const int4*)dst, E4);        // 2
    scan1_kernel<<<NB_SCAN, 1024>>>();                                                       // 3
    gemm1_kernel<<<(N_NODES + G1_BM - 1) / G1_BM, 128>>>(h, W1);                             // 4 (profiled)
    scan2_kernel<<<1, 128>>>();                                                              // 5
    scan3_kernel<<<(N_NODES + 255) / 256, 256>>>();                                          // 6
    scatter_kernel<<<(E4 + 255) / 256, 256>>>((const int4*)src, (const int4*)dst, E4);       // 7
    spmm1_csr_kernel<<<(N_NODES * 32 + 255) / 256, 256>>>(b1);                               // 8
    gemm2_kernel<<<(N_NODES + 127) / 128, 128>>>(W2);                                        // 9
    spmm2_csr_kernel<<<(N_NODES * 32 + 255) / 256, 256>>>(out, b2);                          // 10
}